// round 9
// baseline (speedup 1.0000x reference)
#include <cuda_runtime.h>
#include <cuda_bf16.h>
#include <cstdint>

#define BATCH 8192
#define DIM 10
#define ROWP 12            // padded pooled row: 48B, 16B-aligned
#define LOG2E 1.4426950408889634f

__device__ float g_pooled[BATCH * ROWP];

typedef unsigned long long u64;
typedef unsigned int u32;

__device__ __forceinline__ u64 pack2(float lo, float hi) {
    u64 r; asm("mov.b64 %0, {%1, %2};" : "=l"(r) : "f"(lo), "f"(hi)); return r;
}
__device__ __forceinline__ float2 unpack2(u64 v) {
    float2 f; asm("mov.b64 {%0, %1}, %2;" : "=f"(f.x), "=f"(f.y) : "l"(v)); return f;
}
__device__ __forceinline__ u64 fma2(u64 a, u64 b, u64 c) {
    u64 d; asm("fma.rn.f32x2 %0, %1, %2, %3;" : "=l"(d) : "l"(a), "l"(b), "l"(c)); return d;
}
__device__ __forceinline__ u64 mul2(u64 a, u64 b) {
    u64 d; asm("mul.rn.f32x2 %0, %1, %2;" : "=l"(d) : "l"(a), "l"(b)); return d;
}
__device__ __forceinline__ float ex2f(float x) {
    float y; asm("ex2.approx.f32 %0, %1;" : "=f"(y) : "f"(x)); return y;
}
__device__ __forceinline__ u32 smem_u32(const void* p) {
    u32 a;
    asm("{ .reg .u64 t; cvta.to.shared.u64 t, %1; cvt.u32.u64 %0, t; }"
        : "=r"(a) : "l"(p));
    return a;
}
__device__ __forceinline__ void lds128_2x64(u64& a, u64& b, u32 addr) {
    asm volatile("ld.shared.v2.b64 {%0, %1}, [%2];"
                 : "=l"(a), "=l"(b) : "r"(addr));
}

// ---------------------------------------------------------------------------
// Kernel 1: pooled[b,:] = (sum_n w_n * x[b,n,:]) @ W   (stride-12 padded rows)
// ---------------------------------------------------------------------------
#define PK_NT 128
__global__ __launch_bounds__(PK_NT)
void pooled_kernel(const float* __restrict__ x,
                   const float* __restrict__ A,
                   const float* __restrict__ W) {
    __shared__ float sx[PK_NT * 3 * DIM];
    __shared__ float sW[DIM * DIM];
    __shared__ float sw[3];
    int tid = threadIdx.x;
    if (tid < DIM * DIM) sW[tid] = W[tid];
    if (tid < 3) {
        const float offsum[3] = {1.f, 1.f, 2.f};
        sw[tid] = 0.125f * (offsum[tid] + A[tid] + A[3 + tid]);
    }
    const float4* xs = (const float4*)(x + blockIdx.x * PK_NT * 3 * DIM);
    float4* sd = (float4*)sx;
    #pragma unroll
    for (int i = tid; i < PK_NT * 3 * DIM / 4; i += PK_NT)
        sd[i] = xs[i];
    __syncthreads();

    const float* xb = &sx[tid * 3 * DIM];
    float w0 = sw[0], w1 = sw[1], w2 = sw[2];
    float y[DIM];
    #pragma unroll
    for (int f = 0; f < DIM; f++)
        y[f] = fmaf(w2, xb[2 * DIM + f], fmaf(w1, xb[DIM + f], w0 * xb[f]));
    int b = blockIdx.x * PK_NT + tid;
    #pragma unroll
    for (int o = 0; o < DIM; o++) {
        float acc = 0.f;
        #pragma unroll
        for (int f = 0; f < DIM; f++)
            acc = fmaf(y[f], sW[f * DIM + o], acc);
        g_pooled[b * ROWP + o] = acc;
    }
    g_pooled[b * ROWP + 10] = 0.f;   // pad (keeps SMEM free of NaN surprises)
    g_pooled[b * ROWP + 11] = 0.f;
}

// ---------------------------------------------------------------------------
// Kernel 2: out = softmax(P P^T) P, flash-style.
// NT=256 = 8 warps; PARTS=64 (two warps) per query-quad, QPT=4.
// BQ=16 queries/CTA -> grid=512 (131072 threads; half the key re-traffic of R7).
// Keys in row-major [TILE][12] SMEM (conflict-free LDS.128 x3),
// filled with 16B cp.async (48 warp-ops/tile vs 80 with 8B).
// ---------------------------------------------------------------------------
#define TILE 512
#define NTILES (BATCH / TILE)
#define NT 256
#define PARTS 64
#define QPT 4
#define BQ 16    // (NT/PARTS)*QPT

__global__ __launch_bounds__(NT, 2)
void attn_kernel(float* __restrict__ out) {
    // 2 buffers x TILE x 48B = 49152 B (reduction overlay reuses buffer 0)
    __shared__ __align__(16) float sk[2][TILE * ROWP];

    int tid  = threadIdx.x;
    int grp  = tid >> 6;        // 0..3 : query-quad group (2 warps each)
    int p    = tid & 63;        // key-part within group
    int wid  = tid >> 5;        // warp 0..7
    int lane = tid & 31;
    int myq  = blockIdx.x * BQ + grp * QPT;

    u32 sbase = smem_u32(&sk[0][0]);
    const u32 BUFB = TILE * ROWP * 4;   // 24576 B

    // queries (pre-scaled by log2e)
    u64 q[QPT][5];
    #pragma unroll
    for (int u = 0; u < QPT; u++)
        #pragma unroll
        for (int h = 0; h < 5; h++) {
            float2 v = *(const float2*)&g_pooled[(myq + u) * ROWP + 2 * h];
            q[u][h] = pack2(v.x * LOG2E, v.y * LOG2E);
        }

    u64 acc[QPT][5];
    float esum[QPT];
    #pragma unroll
    for (int u = 0; u < QPT; u++) {
        esum[u] = 0.f;
        #pragma unroll
        for (int h = 0; h < 5; h++) acc[u][h] = pack2(0.f, 0.f);
    }

    // tile fill: 3 x 16B cp.async per 48B row
    auto fill_tile = [&](int t, int buf) {
        const float* src = g_pooled + t * TILE * ROWP;
        u32 dbase = sbase + buf * BUFB;
        #pragma unroll
        for (int r = tid; r < TILE; r += NT) {     // 2 rows per thread
            const float* s = src + r * ROWP;
            u32 d = dbase + r * 48u;
            asm volatile("cp.async.cg.shared.global [%0], [%1], 16;" :: "r"(d),       "l"(s));
            asm volatile("cp.async.cg.shared.global [%0], [%1], 16;" :: "r"(d + 16u), "l"(s + 4));
            asm volatile("cp.async.cg.shared.global [%0], [%1], 16;" :: "r"(d + 32u), "l"(s + 8));
        }
        asm volatile("cp.async.commit_group;");
    };

    fill_tile(0, 0);

    for (int t = 0; t < NTILES; t++) {
        asm volatile("cp.async.wait_group 0;");
        __syncthreads();
        if (t + 1 < NTILES) fill_tile(t + 1, (t + 1) & 1);

        u32 kbase = sbase + (t & 1) * BUFB;
        #pragma unroll
        for (int j = p; j < TILE; j += PARTS) {   // 8 iterations
            u32 oa = kbase + j * 48u;
            u64 k0, k1, k2, k3, k4, kpad;
            lds128_2x64(k0, k1, oa);
            lds128_2x64(k2, k3, oa + 16u);
            lds128_2x64(k4, kpad, oa + 32u);
            (void)kpad;
            // 4 independent dot chains
            u64 s0 = mul2(q[0][0], k0);
            u64 s1 = mul2(q[1][0], k0);
            u64 s2 = mul2(q[2][0], k0);
            u64 s3 = mul2(q[3][0], k0);
            s0 = fma2(q[0][1], k1, s0);
            s1 = fma2(q[1][1], k1, s1);
            s2 = fma2(q[2][1], k1, s2);
            s3 = fma2(q[3][1], k1, s3);
            s0 = fma2(q[0][2], k2, s0);
            s1 = fma2(q[1][2], k2, s1);
            s2 = fma2(q[2][2], k2, s2);
            s3 = fma2(q[3][2], k2, s3);
            s0 = fma2(q[0][3], k3, s0);
            s1 = fma2(q[1][3], k3, s1);
            s2 = fma2(q[2][3], k3, s2);
            s3 = fma2(q[3][3], k3, s3);
            s0 = fma2(q[0][4], k4, s0);
            s1 = fma2(q[1][4], k4, s1);
            s2 = fma2(q[2][4], k4, s2);
            s3 = fma2(q[3][4], k4, s3);
            float2 f0 = unpack2(s0);
            float2 f1 = unpack2(s1);
            float2 f2 = unpack2(s2);
            float2 f3 = unpack2(s3);
            float e0 = ex2f(f0.x + f0.y);
            float e1 = ex2f(f1.x + f1.y);
            float e2 = ex2f(f2.x + f2.y);
            float e3 = ex2f(f3.x + f3.y);
            esum[0] += e0; esum[1] += e1; esum[2] += e2; esum[3] += e3;
            u64 ee0 = pack2(e0, e0);
            u64 ee1 = pack2(e1, e1);
            u64 ee2 = pack2(e2, e2);
            u64 ee3 = pack2(e3, e3);
            acc[0][0] = fma2(ee0, k0, acc[0][0]);
            acc[1][0] = fma2(ee1, k0, acc[1][0]);
            acc[2][0] = fma2(ee2, k0, acc[2][0]);
            acc[3][0] = fma2(ee3, k0, acc[3][0]);
            acc[0][1] = fma2(ee0, k1, acc[0][1]);
            acc[1][1] = fma2(ee1, k1, acc[1][1]);
            acc[2][1] = fma2(ee2, k1, acc[2][1]);
            acc[3][1] = fma2(ee3, k1, acc[3][1]);
            acc[0][2] = fma2(ee0, k2, acc[0][2]);
            acc[1][2] = fma2(ee1, k2, acc[1][2]);
            acc[2][2] = fma2(ee2, k2, acc[2][2]);
            acc[3][2] = fma2(ee3, k2, acc[3][2]);
            acc[0][3] = fma2(ee0, k3, acc[0][3]);
            acc[1][3] = fma2(ee1, k3, acc[1][3]);
            acc[2][3] = fma2(ee2, k3, acc[2][3]);
            acc[3][3] = fma2(ee3, k3, acc[3][3]);
            acc[0][4] = fma2(ee0, k4, acc[0][4]);
            acc[1][4] = fma2(ee1, k4, acc[1][4]);
            acc[2][4] = fma2(ee2, k4, acc[2][4]);
            acc[3][4] = fma2(ee3, k4, acc[3][4]);
        }
    }

    // intra-warp reduction over 32 key-part lanes
    #pragma unroll
    for (int off = 16; off >= 1; off >>= 1) {
        #pragma unroll
        for (int u = 0; u < QPT; u++) {
            esum[u] += __shfl_down_sync(0xffffffffu, esum[u], off);
            #pragma unroll
            for (int h = 0; h < 5; h++) {
                u64 other = __shfl_down_sync(0xffffffffu, acc[u][h], off);
                float2 a = unpack2(acc[u][h]);
                float2 b = unpack2(other);
                acc[u][h] = pack2(a.x + b.x, a.y + b.y);
            }
        }
    }

    // cross-warp combine via SMEM overlay (buffer 0; no cp.async outstanding)
    __syncthreads();
    float* sred = &sk[0][0];    // [warp][u][12]: 10 acc + esum
    if (lane == 0) {
        #pragma unroll
        for (int u = 0; u < QPT; u++) {
            float* dst = sred + (wid * QPT + u) * 12;
            #pragma unroll
            for (int h = 0; h < 5; h++) {
                float2 v = unpack2(acc[u][h]);
                dst[2 * h] = v.x; dst[2 * h + 1] = v.y;
            }
            dst[10] = esum[u];
        }
    }
    __syncthreads();

    // 4 groups x 4 queries x 10 feats = 160 output elements
    if (tid < BQ * DIM) {
        int g = tid / (QPT * DIM);
        int u = (tid / DIM) % QPT;
        int f = tid % DIM;
        const float* w0p = sred + ((2 * g) * QPT + u) * 12;
        const float* w1p = sred + ((2 * g + 1) * QPT + u) * 12;
        float v  = w0p[f] + w1p[f];
        float es = w0p[10] + w1p[10];
        out[(blockIdx.x * BQ + g * QPT + u) * DIM + f] = v / es;
    }
}

// ---------------------------------------------------------------------------
extern "C" void kernel_launch(void* const* d_in, const int* in_sizes, int n_in,
                              void* d_out, int out_size) {
    const float* x = (const float*)d_in[0];   // [8192, 3, 10]
    const float* A = (const float*)d_in[1];   // [3, 3]
    const float* W = (const float*)d_in[2];   // [10, 10]
    float* out = (float*)d_out;               // [8192, 10]

    pooled_kernel<<<BATCH / PK_NT, PK_NT>>>(x, A, W);
    attn_kernel<<<BATCH / BQ, NT>>>(out);
}

// round 11
// speedup vs baseline: 1.4625x; 1.4625x over previous
#include <cuda_runtime.h>
#include <cuda_bf16.h>
#include <cstdint>

#define BATCH 8192
#define DIM 10
#define ROWP 12            // padded pooled row: 48B, 16B-aligned
#define LOG2E 1.4426950408889634f

__device__ float g_pooled[BATCH * ROWP];

typedef unsigned long long u64;
typedef unsigned int u32;

__device__ __forceinline__ u64 pack2(float lo, float hi) {
    u64 r; asm("mov.b64 %0, {%1, %2};" : "=l"(r) : "f"(lo), "f"(hi)); return r;
}
__device__ __forceinline__ float2 unpack2(u64 v) {
    float2 f; asm("mov.b64 {%0, %1}, %2;" : "=f"(f.x), "=f"(f.y) : "l"(v)); return f;
}
__device__ __forceinline__ u64 fma2(u64 a, u64 b, u64 c) {
    u64 d; asm("fma.rn.f32x2 %0, %1, %2, %3;" : "=l"(d) : "l"(a), "l"(b), "l"(c)); return d;
}
__device__ __forceinline__ u64 mul2(u64 a, u64 b) {
    u64 d; asm("mul.rn.f32x2 %0, %1, %2;" : "=l"(d) : "l"(a), "l"(b)); return d;
}
__device__ __forceinline__ float ex2f(float x) {
    float y; asm("ex2.approx.f32 %0, %1;" : "=f"(y) : "f"(x)); return y;
}
__device__ __forceinline__ u32 smem_u32(const void* p) {
    u32 a;
    asm("{ .reg .u64 t; cvta.to.shared.u64 t, %1; cvt.u32.u64 %0, t; }"
        : "=r"(a) : "l"(p));
    return a;
}
__device__ __forceinline__ void lds128_2x64(u64& a, u64& b, u32 addr) {
    asm volatile("ld.shared.v2.b64 {%0, %1}, [%2];"
                 : "=l"(a), "=l"(b) : "r"(addr));
}
__device__ __forceinline__ void mbar_init(u32 mbar, u32 count) {
    asm volatile("mbarrier.init.shared.b64 [%0], %1;" :: "r"(mbar), "r"(count) : "memory");
}
__device__ __forceinline__ void mbar_expect_tx(u32 mbar, u32 bytes) {
    asm volatile("mbarrier.arrive.expect_tx.shared.b64 _, [%0], %1;"
                 :: "r"(mbar), "r"(bytes) : "memory");
}
__device__ __forceinline__ void bulk_g2s(u32 dst, const void* src, u32 bytes, u32 mbar) {
    asm volatile("cp.async.bulk.shared::cta.global.mbarrier::complete_tx::bytes "
                 "[%0], [%1], %2, [%3];"
                 :: "r"(dst), "l"(src), "r"(bytes), "r"(mbar) : "memory");
}
__device__ __forceinline__ void mbar_wait(u32 mbar, u32 parity) {
    asm volatile(
        "{\n\t"
        ".reg .pred P;\n\t"
        "WAIT_%=:\n\t"
        "mbarrier.try_wait.parity.acquire.cta.shared::cta.b64 P, [%0], %1, 0x989680;\n\t"
        "@P bra.uni DONE_%=;\n\t"
        "bra.uni WAIT_%=;\n\t"
        "DONE_%=:\n\t"
        "}"
        :: "r"(mbar), "r"(parity) : "memory");
}

// ---------------------------------------------------------------------------
// Kernel 1: pooled[b,:] = (sum_n w_n * x[b,n,:]) @ W   (stride-12 padded rows)
// ---------------------------------------------------------------------------
#define PK_NT 128
__global__ __launch_bounds__(PK_NT)
void pooled_kernel(const float* __restrict__ x,
                   const float* __restrict__ A,
                   const float* __restrict__ W) {
    __shared__ float sx[PK_NT * 3 * DIM];
    __shared__ float sW[DIM * DIM];
    __shared__ float sw[3];
    int tid = threadIdx.x;
    if (tid < DIM * DIM) sW[tid] = W[tid];
    if (tid < 3) {
        const float offsum[3] = {1.f, 1.f, 2.f};
        sw[tid] = 0.125f * (offsum[tid] + A[tid] + A[3 + tid]);
    }
    const float4* xs = (const float4*)(x + blockIdx.x * PK_NT * 3 * DIM);
    float4* sd = (float4*)sx;
    #pragma unroll
    for (int i = tid; i < PK_NT * 3 * DIM / 4; i += PK_NT)
        sd[i] = xs[i];
    __syncthreads();

    const float* xb = &sx[tid * 3 * DIM];
    float w0 = sw[0], w1 = sw[1], w2 = sw[2];
    float y[DIM];
    #pragma unroll
    for (int f = 0; f < DIM; f++)
        y[f] = fmaf(w2, xb[2 * DIM + f], fmaf(w1, xb[DIM + f], w0 * xb[f]));
    int b = blockIdx.x * PK_NT + tid;
    #pragma unroll
    for (int o = 0; o < DIM; o++) {
        float acc = 0.f;
        #pragma unroll
        for (int f = 0; f < DIM; f++)
            acc = fmaf(y[f], sW[f * DIM + o], acc);
        g_pooled[b * ROWP + o] = acc;
    }
    g_pooled[b * ROWP + 10] = 0.f;
    g_pooled[b * ROWP + 11] = 0.f;
}

// ---------------------------------------------------------------------------
// Kernel 2: out = softmax(P P^T) P, flash-style.
// R7 shape (NT=128, BQ=8, grid=1024, QPT=4, PARTS=64) + single-thread
// cp.async.bulk tile fills (contiguous 24KB per tile) with mbarriers.
// ---------------------------------------------------------------------------
#define TILE 512
#define NTILES (BATCH / TILE)
#define NT 128
#define PARTS 64
#define QPT 4
#define BQ 8     // (NT/PARTS)*QPT

#define TILE_BYTES (TILE * ROWP * 4)   // 24576

__global__ __launch_bounds__(NT)
void attn_kernel(float* __restrict__ out) {
    __shared__ __align__(16) float sk[2][TILE * ROWP];   // 48 KB
    __shared__ __align__(8) u64 mbar_store[2];

    int tid  = threadIdx.x;
    int grp  = tid >> 6;        // 0..1 : query-quad group (2 warps)
    int p    = tid & 63;        // key-part within group
    int wid  = tid >> 5;        // warp 0..3
    int lane = tid & 31;
    int myq  = blockIdx.x * BQ + grp * QPT;

    u32 sbase = smem_u32(&sk[0][0]);
    u32 mbar0 = smem_u32(&mbar_store[0]);
    u32 mbar1 = mbar0 + 8;

    if (tid == 0) {
        mbar_init(mbar0, 1);
        mbar_init(mbar1, 1);
    }
    __syncthreads();

    // queries (pre-scaled by log2e)
    u64 q[QPT][5];
    #pragma unroll
    for (int u = 0; u < QPT; u++)
        #pragma unroll
        for (int h = 0; h < 5; h++) {
            float2 v = *(const float2*)&g_pooled[(myq + u) * ROWP + 2 * h];
            q[u][h] = pack2(v.x * LOG2E, v.y * LOG2E);
        }

    u64 acc[QPT][5];
    float esum[QPT];
    #pragma unroll
    for (int u = 0; u < QPT; u++) {
        esum[u] = 0.f;
        #pragma unroll
        for (int h = 0; h < 5; h++) acc[u][h] = pack2(0.f, 0.f);
    }

    // kick tile 0 into buffer 0
    if (tid == 0) {
        mbar_expect_tx(mbar0, TILE_BYTES);
        bulk_g2s(sbase, g_pooled, TILE_BYTES, mbar0);
    }

    for (int t = 0; t < NTILES; t++) {
        int b = t & 1;
        // prefetch next tile into the other buffer (free: consumed at t-1,
        // guarded by the __syncthreads at the end of iteration t-1)
        if (t + 1 < NTILES && tid == 0) {
            u32 mb = (b ? mbar0 : mbar1);
            mbar_expect_tx(mb, TILE_BYTES);
            bulk_g2s(sbase + (1 - b) * TILE_BYTES,
                     g_pooled + (t + 1) * TILE * ROWP, TILE_BYTES, mb);
        }
        mbar_wait(b ? mbar1 : mbar0, (t >> 1) & 1);

        u32 kbase = sbase + b * TILE_BYTES;
        #pragma unroll
        for (int j = p; j < TILE; j += PARTS) {   // 8 iterations
            u32 oa = kbase + j * 48u;
            u64 k0, k1, k2, k3, k4, kpad;
            lds128_2x64(k0, k1, oa);
            lds128_2x64(k2, k3, oa + 16u);
            lds128_2x64(k4, kpad, oa + 32u);
            (void)kpad;
            u64 s0 = mul2(q[0][0], k0);
            u64 s1 = mul2(q[1][0], k0);
            u64 s2 = mul2(q[2][0], k0);
            u64 s3 = mul2(q[3][0], k0);
            s0 = fma2(q[0][1], k1, s0);
            s1 = fma2(q[1][1], k1, s1);
            s2 = fma2(q[2][1], k1, s2);
            s3 = fma2(q[3][1], k1, s3);
            s0 = fma2(q[0][2], k2, s0);
            s1 = fma2(q[1][2], k2, s1);
            s2 = fma2(q[2][2], k2, s2);
            s3 = fma2(q[3][2], k2, s3);
            s0 = fma2(q[0][3], k3, s0);
            s1 = fma2(q[1][3], k3, s1);
            s2 = fma2(q[2][3], k3, s2);
            s3 = fma2(q[3][3], k3, s3);
            s0 = fma2(q[0][4], k4, s0);
            s1 = fma2(q[1][4], k4, s1);
            s2 = fma2(q[2][4], k4, s2);
            s3 = fma2(q[3][4], k4, s3);
            float2 f0 = unpack2(s0);
            float2 f1 = unpack2(s1);
            float2 f2 = unpack2(s2);
            float2 f3 = unpack2(s3);
            float e0 = ex2f(f0.x + f0.y);
            float e1 = ex2f(f1.x + f1.y);
            float e2 = ex2f(f2.x + f2.y);
            float e3 = ex2f(f3.x + f3.y);
            esum[0] += e0; esum[1] += e1; esum[2] += e2; esum[3] += e3;
            u64 ee0 = pack2(e0, e0);
            u64 ee1 = pack2(e1, e1);
            u64 ee2 = pack2(e2, e2);
            u64 ee3 = pack2(e3, e3);
            acc[0][0] = fma2(ee0, k0, acc[0][0]);
            acc[1][0] = fma2(ee1, k0, acc[1][0]);
            acc[2][0] = fma2(ee2, k0, acc[2][0]);
            acc[3][0] = fma2(ee3, k0, acc[3][0]);
            acc[0][1] = fma2(ee0, k1, acc[0][1]);
            acc[1][1] = fma2(ee1, k1, acc[1][1]);
            acc[2][1] = fma2(ee2, k1, acc[2][1]);
            acc[3][1] = fma2(ee3, k1, acc[3][1]);
            acc[0][2] = fma2(ee0, k2, acc[0][2]);
            acc[1][2] = fma2(ee1, k2, acc[1][2]);
            acc[2][2] = fma2(ee2, k2, acc[2][2]);
            acc[3][2] = fma2(ee3, k2, acc[3][2]);
            acc[0][3] = fma2(ee0, k3, acc[0][3]);
            acc[1][3] = fma2(ee1, k3, acc[1][3]);
            acc[2][3] = fma2(ee2, k3, acc[2][3]);
            acc[3][3] = fma2(ee3, k3, acc[3][3]);
            acc[0][4] = fma2(ee0, k4, acc[0][4]);
            acc[1][4] = fma2(ee1, k4, acc[1][4]);
            acc[2][4] = fma2(ee2, k4, acc[2][4]);
            acc[3][4] = fma2(ee3, k4, acc[3][4]);
        }
        __syncthreads();   // all threads done with buffer b before refill
    }

    // intra-warp reduction over 32 key-part lanes
    #pragma unroll
    for (int off = 16; off >= 1; off >>= 1) {
        #pragma unroll
        for (int u = 0; u < QPT; u++) {
            esum[u] += __shfl_down_sync(0xffffffffu, esum[u], off);
            #pragma unroll
            for (int h = 0; h < 5; h++) {
                u64 other = __shfl_down_sync(0xffffffffu, acc[u][h], off);
                float2 a = unpack2(acc[u][h]);
                float2 bb = unpack2(other);
                acc[u][h] = pack2(a.x + bb.x, a.y + bb.y);
            }
        }
    }

    // cross-warp combine via SMEM overlay (all tile reads done)
    float* sred = &sk[0][0];    // [warp][u][12]: 10 acc + esum
    if (lane == 0) {
        #pragma unroll
        for (int u = 0; u < QPT; u++) {
            float* dst = sred + (wid * QPT + u) * 12;
            #pragma unroll
            for (int h = 0; h < 5; h++) {
                float2 v = unpack2(acc[u][h]);
                dst[2 * h] = v.x; dst[2 * h + 1] = v.y;
            }
            dst[10] = esum[u];
        }
    }
    __syncthreads();

    // 2 groups x 4 queries x 10 feats = 80 output elements
    if (tid < BQ * DIM) {
        int g = tid / (QPT * DIM);
        int u = (tid / DIM) % QPT;
        int f = tid % DIM;
        const float* w0p = sred + ((2 * g) * QPT + u) * 12;
        const float* w1p = sred + ((2 * g + 1) * QPT + u) * 12;
        float v  = w0p[f] + w1p[f];
        float es = w0p[10] + w1p[10];
        out[(blockIdx.x * BQ + g * QPT + u) * DIM + f] = v / es;
    }
}

// ---------------------------------------------------------------------------
extern "C" void kernel_launch(void* const* d_in, const int* in_sizes, int n_in,
                              void* d_out, int out_size) {
    const float* x = (const float*)d_in[0];   // [8192, 3, 10]
    const float* A = (const float*)d_in[1];   // [3, 3]
    const float* W = (const float*)d_in[2];   // [10, 10]
    float* out = (float*)d_out;               // [8192, 10]

    pooled_kernel<<<BATCH / PK_NT, PK_NT>>>(x, A, W);
    attn_kernel<<<BATCH / BQ, NT>>>(out);
}

// round 12
// speedup vs baseline: 1.5055x; 1.0294x over previous
#include <cuda_runtime.h>
#include <cuda_bf16.h>
#include <cstdint>

#define BATCH 8192
#define DIM 10
#define ROWP 12            // padded pooled row: 48B, 16B-aligned
#define LOG2E 1.4426950408889634f

__device__ float g_pooled[BATCH * ROWP];

typedef unsigned long long u64;
typedef unsigned int u32;

__device__ __forceinline__ u64 pack2(float lo, float hi) {
    u64 r; asm("mov.b64 %0, {%1, %2};" : "=l"(r) : "f"(lo), "f"(hi)); return r;
}
__device__ __forceinline__ float2 unpack2(u64 v) {
    float2 f; asm("mov.b64 {%0, %1}, %2;" : "=f"(f.x), "=f"(f.y) : "l"(v)); return f;
}
__device__ __forceinline__ u64 fma2(u64 a, u64 b, u64 c) {
    u64 d; asm("fma.rn.f32x2 %0, %1, %2, %3;" : "=l"(d) : "l"(a), "l"(b), "l"(c)); return d;
}
__device__ __forceinline__ u64 mul2(u64 a, u64 b) {
    u64 d; asm("mul.rn.f32x2 %0, %1, %2;" : "=l"(d) : "l"(a), "l"(b)); return d;
}
__device__ __forceinline__ u64 add2(u64 a, u64 b) {
    u64 d; asm("add.rn.f32x2 %0, %1, %2;" : "=l"(d) : "l"(a), "l"(b)); return d;
}
__device__ __forceinline__ float ex2f(float x) {
    float y; asm("ex2.approx.f32 %0, %1;" : "=f"(y) : "f"(x)); return y;
}
__device__ __forceinline__ u32 smem_u32(const void* p) {
    u32 a;
    asm("{ .reg .u64 t; cvta.to.shared.u64 t, %1; cvt.u32.u64 %0, t; }"
        : "=r"(a) : "l"(p));
    return a;
}
__device__ __forceinline__ void lds128_2x64(u64& a, u64& b, u32 addr) {
    asm volatile("ld.shared.v2.b64 {%0, %1}, [%2];"
                 : "=l"(a), "=l"(b) : "r"(addr));
}
__device__ __forceinline__ u64 lds64(u32 addr) {
    u64 v; asm volatile("ld.shared.b64 %0, [%1];" : "=l"(v) : "r"(addr)); return v;
}
__device__ __forceinline__ void mbar_init(u32 mbar, u32 count) {
    asm volatile("mbarrier.init.shared.b64 [%0], %1;" :: "r"(mbar), "r"(count) : "memory");
}
__device__ __forceinline__ void mbar_expect_tx(u32 mbar, u32 bytes) {
    asm volatile("mbarrier.arrive.expect_tx.shared.b64 _, [%0], %1;"
                 :: "r"(mbar), "r"(bytes) : "memory");
}
__device__ __forceinline__ void bulk_g2s(u32 dst, const void* src, u32 bytes, u32 mbar) {
    asm volatile("cp.async.bulk.shared::cta.global.mbarrier::complete_tx::bytes "
                 "[%0], [%1], %2, [%3];"
                 :: "r"(dst), "l"(src), "r"(bytes), "r"(mbar) : "memory");
}
__device__ __forceinline__ void mbar_wait(u32 mbar, u32 parity) {
    asm volatile(
        "{\n\t"
        ".reg .pred P;\n\t"
        "WAIT_%=:\n\t"
        "mbarrier.try_wait.parity.acquire.cta.shared::cta.b64 P, [%0], %1, 0x989680;\n\t"
        "@P bra.uni DONE_%=;\n\t"
        "bra.uni WAIT_%=;\n\t"
        "DONE_%=:\n\t"
        "}"
        :: "r"(mbar), "r"(parity) : "memory");
}

// ---------------------------------------------------------------------------
// Kernel 1: pooled[b,:] = (sum_n w_n * x[b,n,:]) @ W   (stride-12 padded rows)
// ---------------------------------------------------------------------------
#define PK_NT 128
__global__ __launch_bounds__(PK_NT)
void pooled_kernel(const float* __restrict__ x,
                   const float* __restrict__ A,
                   const float* __restrict__ W) {
    __shared__ float sx[PK_NT * 3 * DIM];
    __shared__ float sW[DIM * DIM];
    __shared__ float sw[3];
    int tid = threadIdx.x;
    if (tid < DIM * DIM) sW[tid] = W[tid];
    if (tid < 3) {
        const float offsum[3] = {1.f, 1.f, 2.f};
        sw[tid] = 0.125f * (offsum[tid] + A[tid] + A[3 + tid]);
    }
    const float4* xs = (const float4*)(x + blockIdx.x * PK_NT * 3 * DIM);
    float4* sd = (float4*)sx;
    #pragma unroll
    for (int i = tid; i < PK_NT * 3 * DIM / 4; i += PK_NT)
        sd[i] = xs[i];
    __syncthreads();

    const float* xb = &sx[tid * 3 * DIM];
    float w0 = sw[0], w1 = sw[1], w2 = sw[2];
    float y[DIM];
    #pragma unroll
    for (int f = 0; f < DIM; f++)
        y[f] = fmaf(w2, xb[2 * DIM + f], fmaf(w1, xb[DIM + f], w0 * xb[f]));
    int b = blockIdx.x * PK_NT + tid;
    #pragma unroll
    for (int o = 0; o < DIM; o++) {
        float acc = 0.f;
        #pragma unroll
        for (int f = 0; f < DIM; f++)
            acc = fmaf(y[f], sW[f * DIM + o], acc);
        g_pooled[b * ROWP + o] = acc;
    }
    g_pooled[b * ROWP + 10] = 0.f;
    g_pooled[b * ROWP + 11] = 0.f;
}

// ---------------------------------------------------------------------------
// Kernel 2: out = softmax(P P^T) P, flash-style.
// NT=128, BQ=8, grid=1024, QPT=4, PARTS=64; single-thread cp.async.bulk
// fills + mbarriers. R11: regs<=128 (4 CTA/SM), packed esum accumulators.
// ---------------------------------------------------------------------------
#define TILE 512
#define NTILES (BATCH / TILE)
#define NT 128
#define PARTS 64
#define QPT 4
#define BQ 8     // (NT/PARTS)*QPT

#define TILE_BYTES (TILE * ROWP * 4)   // 24576

__global__ __launch_bounds__(NT, 4)
void attn_kernel(float* __restrict__ out) {
    __shared__ __align__(16) float sk[2][TILE * ROWP];   // 48 KB
    __shared__ __align__(8) u64 mbar_store[2];

    int tid  = threadIdx.x;
    int grp  = tid >> 6;        // 0..1 : query-quad group (2 warps)
    int p    = tid & 63;        // key-part within group
    int wid  = tid >> 5;        // warp 0..3
    int lane = tid & 31;
    int myq  = blockIdx.x * BQ + grp * QPT;

    u32 sbase = smem_u32(&sk[0][0]);
    u32 mbar0 = smem_u32(&mbar_store[0]);
    u32 mbar1 = mbar0 + 8;

    if (tid == 0) {
        mbar_init(mbar0, 1);
        mbar_init(mbar1, 1);
    }
    __syncthreads();

    // queries (pre-scaled by log2e)
    u64 q[QPT][5];
    #pragma unroll
    for (int u = 0; u < QPT; u++)
        #pragma unroll
        for (int h = 0; h < 5; h++) {
            float2 v = *(const float2*)&g_pooled[(myq + u) * ROWP + 2 * h];
            q[u][h] = pack2(v.x * LOG2E, v.y * LOG2E);
        }

    u64 acc[QPT][5];
    u64 esum01 = pack2(0.f, 0.f);
    u64 esum23 = pack2(0.f, 0.f);
    #pragma unroll
    for (int u = 0; u < QPT; u++)
        #pragma unroll
        for (int h = 0; h < 5; h++) acc[u][h] = pack2(0.f, 0.f);

    // kick tile 0 into buffer 0
    if (tid == 0) {
        mbar_expect_tx(mbar0, TILE_BYTES);
        bulk_g2s(sbase, g_pooled, TILE_BYTES, mbar0);
    }

    for (int t = 0; t < NTILES; t++) {
        int b = t & 1;
        if (t + 1 < NTILES && tid == 0) {
            u32 mb = (b ? mbar0 : mbar1);
            mbar_expect_tx(mb, TILE_BYTES);
            bulk_g2s(sbase + (1 - b) * TILE_BYTES,
                     g_pooled + (t + 1) * TILE * ROWP, TILE_BYTES, mb);
        }
        mbar_wait(b ? mbar1 : mbar0, (t >> 1) & 1);

        u32 kbase = sbase + b * TILE_BYTES;
        #pragma unroll
        for (int j = p; j < TILE; j += PARTS) {   // 8 iterations
            u32 oa = kbase + j * 48u;
            u64 k0, k1, k2, k3;
            lds128_2x64(k0, k1, oa);
            lds128_2x64(k2, k3, oa + 16u);
            u64 k4 = lds64(oa + 32u);
            u64 s0 = mul2(q[0][0], k0);
            u64 s1 = mul2(q[1][0], k0);
            u64 s2 = mul2(q[2][0], k0);
            u64 s3 = mul2(q[3][0], k0);
            s0 = fma2(q[0][1], k1, s0);
            s1 = fma2(q[1][1], k1, s1);
            s2 = fma2(q[2][1], k1, s2);
            s3 = fma2(q[3][1], k1, s3);
            s0 = fma2(q[0][2], k2, s0);
            s1 = fma2(q[1][2], k2, s1);
            s2 = fma2(q[2][2], k2, s2);
            s3 = fma2(q[3][2], k2, s3);
            s0 = fma2(q[0][3], k3, s0);
            s1 = fma2(q[1][3], k3, s1);
            s2 = fma2(q[2][3], k3, s2);
            s3 = fma2(q[3][3], k3, s3);
            s0 = fma2(q[0][4], k4, s0);
            s1 = fma2(q[1][4], k4, s1);
            s2 = fma2(q[2][4], k4, s2);
            s3 = fma2(q[3][4], k4, s3);
            float2 f0 = unpack2(s0);
            float2 f1 = unpack2(s1);
            float2 f2 = unpack2(s2);
            float2 f3 = unpack2(s3);
            float e0 = ex2f(f0.x + f0.y);
            float e1 = ex2f(f1.x + f1.y);
            float e2 = ex2f(f2.x + f2.y);
            float e3 = ex2f(f3.x + f3.y);
            esum01 = add2(esum01, pack2(e0, e1));
            esum23 = add2(esum23, pack2(e2, e3));
            u64 ee0 = pack2(e0, e0);
            u64 ee1 = pack2(e1, e1);
            u64 ee2 = pack2(e2, e2);
            u64 ee3 = pack2(e3, e3);
            acc[0][0] = fma2(ee0, k0, acc[0][0]);
            acc[1][0] = fma2(ee1, k0, acc[1][0]);
            acc[2][0] = fma2(ee2, k0, acc[2][0]);
            acc[3][0] = fma2(ee3, k0, acc[3][0]);
            acc[0][1] = fma2(ee0, k1, acc[0][1]);
            acc[1][1] = fma2(ee1, k1, acc[1][1]);
            acc[2][1] = fma2(ee2, k1, acc[2][1]);
            acc[3][1] = fma2(ee3, k1, acc[3][1]);
            acc[0][2] = fma2(ee0, k2, acc[0][2]);
            acc[1][2] = fma2(ee1, k2, acc[1][2]);
            acc[2][2] = fma2(ee2, k2, acc[2][2]);
            acc[3][2] = fma2(ee3, k2, acc[3][2]);
            acc[0][3] = fma2(ee0, k3, acc[0][3]);
            acc[1][3] = fma2(ee1, k3, acc[1][3]);
            acc[2][3] = fma2(ee2, k3, acc[2][3]);
            acc[3][3] = fma2(ee3, k3, acc[3][3]);
            acc[0][4] = fma2(ee0, k4, acc[0][4]);
            acc[1][4] = fma2(ee1, k4, acc[1][4]);
            acc[2][4] = fma2(ee2, k4, acc[2][4]);
            acc[3][4] = fma2(ee3, k4, acc[3][4]);
        }
        __syncthreads();   // all threads done with buffer b before refill
    }

    // intra-warp reduction over 32 key-part lanes
    #pragma unroll
    for (int off = 16; off >= 1; off >>= 1) {
        {
            u64 o01 = __shfl_down_sync(0xffffffffu, esum01, off);
            u64 o23 = __shfl_down_sync(0xffffffffu, esum23, off);
            esum01 = add2(esum01, o01);
            esum23 = add2(esum23, o23);
        }
        #pragma unroll
        for (int u = 0; u < QPT; u++)
            #pragma unroll
            for (int h = 0; h < 5; h++) {
                u64 other = __shfl_down_sync(0xffffffffu, acc[u][h], off);
                acc[u][h] = add2(acc[u][h], other);
            }
    }

    // cross-warp combine via SMEM overlay (all tile reads done)
    float* sred = &sk[0][0];    // [warp][u][12]: 10 acc + esum
    if (lane == 0) {
        float2 es01 = unpack2(esum01);
        float2 es23 = unpack2(esum23);
        float est[QPT] = {es01.x, es01.y, es23.x, es23.y};
        #pragma unroll
        for (int u = 0; u < QPT; u++) {
            float* dst = sred + (wid * QPT + u) * 12;
            #pragma unroll
            for (int h = 0; h < 5; h++) {
                float2 v = unpack2(acc[u][h]);
                dst[2 * h] = v.x; dst[2 * h + 1] = v.y;
            }
            dst[10] = est[u];
        }
    }
    __syncthreads();

    // 2 groups x 4 queries x 10 feats = 80 output elements
    if (tid < BQ * DIM) {
        int g = tid / (QPT * DIM);
        int u = (tid / DIM) % QPT;
        int f = tid % DIM;
        const float* w0p = sred + ((2 * g) * QPT + u) * 12;
        const float* w1p = sred + ((2 * g + 1) * QPT + u) * 12;
        float v  = w0p[f] + w1p[f];
        float es = w0p[10] + w1p[10];
        out[(blockIdx.x * BQ + g * QPT + u) * DIM + f] = v / es;
    }
}

// ---------------------------------------------------------------------------
extern "C" void kernel_launch(void* const* d_in, const int* in_sizes, int n_in,
                              void* d_out, int out_size) {
    const float* x = (const float*)d_in[0];   // [8192, 3, 10]
    const float* A = (const float*)d_in[1];   // [3, 3]
    const float* W = (const float*)d_in[2];   // [10, 10]
    float* out = (float*)d_out;               // [8192, 10]

    pooled_kernel<<<BATCH / PK_NT, PK_NT>>>(x, A, W);
    attn_kernel<<<BATCH / BQ, NT>>>(out);
}

// round 13
// speedup vs baseline: 1.5358x; 1.0201x over previous
#include <cuda_runtime.h>
#include <cuda_bf16.h>
#include <cstdint>

#define BATCH 8192
#define DIM 10
#define ROWP 12            // padded pooled row: 48B, 16B-aligned
#define LOG2E 1.4426950408889634f

__device__ float g_pooled[BATCH * ROWP];

typedef unsigned long long u64;
typedef unsigned int u32;

__device__ __forceinline__ u64 pack2(float lo, float hi) {
    u64 r; asm("mov.b64 %0, {%1, %2};" : "=l"(r) : "f"(lo), "f"(hi)); return r;
}
__device__ __forceinline__ float2 unpack2(u64 v) {
    float2 f; asm("mov.b64 {%0, %1}, %2;" : "=f"(f.x), "=f"(f.y) : "l"(v)); return f;
}
__device__ __forceinline__ u64 fma2(u64 a, u64 b, u64 c) {
    u64 d; asm("fma.rn.f32x2 %0, %1, %2, %3;" : "=l"(d) : "l"(a), "l"(b), "l"(c)); return d;
}
__device__ __forceinline__ u64 mul2(u64 a, u64 b) {
    u64 d; asm("mul.rn.f32x2 %0, %1, %2;" : "=l"(d) : "l"(a), "l"(b)); return d;
}
__device__ __forceinline__ u64 add2(u64 a, u64 b) {
    u64 d; asm("add.rn.f32x2 %0, %1, %2;" : "=l"(d) : "l"(a), "l"(b)); return d;
}
__device__ __forceinline__ float ex2f(float x) {
    float y; asm("ex2.approx.f32 %0, %1;" : "=f"(y) : "f"(x)); return y;
}
__device__ __forceinline__ u32 smem_u32(const void* p) {
    u32 a;
    asm("{ .reg .u64 t; cvta.to.shared.u64 t, %1; cvt.u32.u64 %0, t; }"
        : "=r"(a) : "l"(p));
    return a;
}
__device__ __forceinline__ void lds128_2x64(u64& a, u64& b, u32 addr) {
    asm volatile("ld.shared.v2.b64 {%0, %1}, [%2];"
                 : "=l"(a), "=l"(b) : "r"(addr));
}
__device__ __forceinline__ u64 lds64(u32 addr) {
    u64 v; asm volatile("ld.shared.b64 %0, [%1];" : "=l"(v) : "r"(addr)); return v;
}
__device__ __forceinline__ void mbar_init(u32 mbar, u32 count) {
    asm volatile("mbarrier.init.shared.b64 [%0], %1;" :: "r"(mbar), "r"(count) : "memory");
}
__device__ __forceinline__ void mbar_expect_tx(u32 mbar, u32 bytes) {
    asm volatile("mbarrier.arrive.expect_tx.shared.b64 _, [%0], %1;"
                 :: "r"(mbar), "r"(bytes) : "memory");
}
__device__ __forceinline__ void bulk_g2s(u32 dst, const void* src, u32 bytes, u32 mbar) {
    asm volatile("cp.async.bulk.shared::cta.global.mbarrier::complete_tx::bytes "
                 "[%0], [%1], %2, [%3];"
                 :: "r"(dst), "l"(src), "r"(bytes), "r"(mbar) : "memory");
}
__device__ __forceinline__ void mbar_wait(u32 mbar, u32 parity) {
    asm volatile(
        "{\n\t"
        ".reg .pred P;\n\t"
        "WAIT_%=:\n\t"
        "mbarrier.try_wait.parity.acquire.cta.shared::cta.b64 P, [%0], %1, 0x989680;\n\t"
        "@P bra.uni DONE_%=;\n\t"
        "bra.uni WAIT_%=;\n\t"
        "DONE_%=:\n\t"
        "}"
        :: "r"(mbar), "r"(parity) : "memory");
}

// ---------------------------------------------------------------------------
// Kernel 1: pooled[b,:] = (sum_n w_n * x[b,n,:]) @ W   (stride-12 padded rows)
// ---------------------------------------------------------------------------
#define PK_NT 128
__global__ __launch_bounds__(PK_NT)
void pooled_kernel(const float* __restrict__ x,
                   const float* __restrict__ A,
                   const float* __restrict__ W) {
    __shared__ float sx[PK_NT * 3 * DIM];
    __shared__ float sW[DIM * DIM];
    __shared__ float sw[3];
    int tid = threadIdx.x;
    if (tid < DIM * DIM) sW[tid] = W[tid];
    if (tid < 3) {
        const float offsum[3] = {1.f, 1.f, 2.f};
        sw[tid] = 0.125f * (offsum[tid] + A[tid] + A[3 + tid]);
    }
    const float4* xs = (const float4*)(x + blockIdx.x * PK_NT * 3 * DIM);
    float4* sd = (float4*)sx;
    #pragma unroll
    for (int i = tid; i < PK_NT * 3 * DIM / 4; i += PK_NT)
        sd[i] = xs[i];
    __syncthreads();

    const float* xb = &sx[tid * 3 * DIM];
    float w0 = sw[0], w1 = sw[1], w2 = sw[2];
    float y[DIM];
    #pragma unroll
    for (int f = 0; f < DIM; f++)
        y[f] = fmaf(w2, xb[2 * DIM + f], fmaf(w1, xb[DIM + f], w0 * xb[f]));
    int b = blockIdx.x * PK_NT + tid;
    #pragma unroll
    for (int o = 0; o < DIM; o++) {
        float acc = 0.f;
        #pragma unroll
        for (int f = 0; f < DIM; f++)
            acc = fmaf(y[f], sW[f * DIM + o], acc);
        g_pooled[b * ROWP + o] = acc;
    }
    g_pooled[b * ROWP + 10] = 0.f;
    g_pooled[b * ROWP + 11] = 0.f;
}

// ---------------------------------------------------------------------------
// Kernel 2: out = softmax(P P^T) P, flash-style.
// NT=128, BQ=8, grid=1024, QPT=4, PARTS=64; cp.async.bulk fills + mbarriers.
// R12: software-pipelined key loads (prefetch j+1 before exp/acc of j).
// ---------------------------------------------------------------------------
#define TILE 512
#define NTILES (BATCH / TILE)
#define NT 128
#define PARTS 64
#define QPT 4
#define BQ 8     // (NT/PARTS)*QPT
#define JITER (TILE / PARTS)   // 8

#define TILE_BYTES (TILE * ROWP * 4)   // 24576

__global__ __launch_bounds__(NT, 4)
void attn_kernel(float* __restrict__ out) {
    __shared__ __align__(16) float sk[2][TILE * ROWP];   // 48 KB
    __shared__ __align__(8) u64 mbar_store[2];

    int tid  = threadIdx.x;
    int grp  = tid >> 6;        // 0..1 : query-quad group (2 warps)
    int p    = tid & 63;        // key-part within group
    int wid  = tid >> 5;        // warp 0..3
    int lane = tid & 31;
    int myq  = blockIdx.x * BQ + grp * QPT;

    u32 sbase = smem_u32(&sk[0][0]);
    u32 mbar0 = smem_u32(&mbar_store[0]);
    u32 mbar1 = mbar0 + 8;

    if (tid == 0) {
        mbar_init(mbar0, 1);
        mbar_init(mbar1, 1);
    }
    __syncthreads();

    // queries (pre-scaled by log2e)
    u64 q[QPT][5];
    #pragma unroll
    for (int u = 0; u < QPT; u++)
        #pragma unroll
        for (int h = 0; h < 5; h++) {
            float2 v = *(const float2*)&g_pooled[(myq + u) * ROWP + 2 * h];
            q[u][h] = pack2(v.x * LOG2E, v.y * LOG2E);
        }

    u64 acc[QPT][5];
    u64 esum01 = pack2(0.f, 0.f);
    u64 esum23 = pack2(0.f, 0.f);
    #pragma unroll
    for (int u = 0; u < QPT; u++)
        #pragma unroll
        for (int h = 0; h < 5; h++) acc[u][h] = pack2(0.f, 0.f);

    // kick tile 0 into buffer 0
    if (tid == 0) {
        mbar_expect_tx(mbar0, TILE_BYTES);
        bulk_g2s(sbase, g_pooled, TILE_BYTES, mbar0);
    }

    for (int t = 0; t < NTILES; t++) {
        int b = t & 1;
        if (t + 1 < NTILES && tid == 0) {
            u32 mb = (b ? mbar0 : mbar1);
            mbar_expect_tx(mb, TILE_BYTES);
            bulk_g2s(sbase + (1 - b) * TILE_BYTES,
                     g_pooled + (t + 1) * TILE * ROWP, TILE_BYTES, mb);
        }
        mbar_wait(b ? mbar1 : mbar0, (t >> 1) & 1);

        u32 addr = sbase + b * TILE_BYTES + p * 48u;

        // prologue: load keys for first iteration
        u64 kc[5];
        lds128_2x64(kc[0], kc[1], addr);
        lds128_2x64(kc[2], kc[3], addr + 16u);
        kc[4] = lds64(addr + 32u);

        #pragma unroll
        for (int it = 0; it < JITER; it++) {
            // prefetch next iteration's keys (hides LDS latency behind exp/acc)
            u64 kn[5];
            if (it + 1 < JITER) {
                u32 na = addr + (u32)((it + 1) * (PARTS * 48));
                lds128_2x64(kn[0], kn[1], na);
                lds128_2x64(kn[2], kn[3], na + 16u);
                kn[4] = lds64(na + 32u);
            }

            u64 s0 = mul2(q[0][0], kc[0]);
            u64 s1 = mul2(q[1][0], kc[0]);
            u64 s2 = mul2(q[2][0], kc[0]);
            u64 s3 = mul2(q[3][0], kc[0]);
            s0 = fma2(q[0][1], kc[1], s0);
            s1 = fma2(q[1][1], kc[1], s1);
            s2 = fma2(q[2][1], kc[1], s2);
            s3 = fma2(q[3][1], kc[1], s3);
            s0 = fma2(q[0][2], kc[2], s0);
            s1 = fma2(q[1][2], kc[2], s1);
            s2 = fma2(q[2][2], kc[2], s2);
            s3 = fma2(q[3][2], kc[2], s3);
            s0 = fma2(q[0][3], kc[3], s0);
            s1 = fma2(q[1][3], kc[3], s1);
            s2 = fma2(q[2][3], kc[3], s2);
            s3 = fma2(q[3][3], kc[3], s3);
            s0 = fma2(q[0][4], kc[4], s0);
            s1 = fma2(q[1][4], kc[4], s1);
            s2 = fma2(q[2][4], kc[4], s2);
            s3 = fma2(q[3][4], kc[4], s3);
            float2 f0 = unpack2(s0);
            float2 f1 = unpack2(s1);
            float2 f2 = unpack2(s2);
            float2 f3 = unpack2(s3);
            float e0 = ex2f(f0.x + f0.y);
            float e1 = ex2f(f1.x + f1.y);
            float e2 = ex2f(f2.x + f2.y);
            float e3 = ex2f(f3.x + f3.y);
            esum01 = add2(esum01, pack2(e0, e1));
            esum23 = add2(esum23, pack2(e2, e3));
            u64 ee0 = pack2(e0, e0);
            u64 ee1 = pack2(e1, e1);
            u64 ee2 = pack2(e2, e2);
            u64 ee3 = pack2(e3, e3);
            acc[0][0] = fma2(ee0, kc[0], acc[0][0]);
            acc[1][0] = fma2(ee1, kc[0], acc[1][0]);
            acc[2][0] = fma2(ee2, kc[0], acc[2][0]);
            acc[3][0] = fma2(ee3, kc[0], acc[3][0]);
            acc[0][1] = fma2(ee0, kc[1], acc[0][1]);
            acc[1][1] = fma2(ee1, kc[1], acc[1][1]);
            acc[2][1] = fma2(ee2, kc[1], acc[2][1]);
            acc[3][1] = fma2(ee3, kc[1], acc[3][1]);
            acc[0][2] = fma2(ee0, kc[2], acc[0][2]);
            acc[1][2] = fma2(ee1, kc[2], acc[1][2]);
            acc[2][2] = fma2(ee2, kc[2], acc[2][2]);
            acc[3][2] = fma2(ee3, kc[2], acc[3][2]);
            acc[0][3] = fma2(ee0, kc[3], acc[0][3]);
            acc[1][3] = fma2(ee1, kc[3], acc[1][3]);
            acc[2][3] = fma2(ee2, kc[3], acc[2][3]);
            acc[3][3] = fma2(ee3, kc[3], acc[3][3]);
            acc[0][4] = fma2(ee0, kc[4], acc[0][4]);
            acc[1][4] = fma2(ee1, kc[4], acc[1][4]);
            acc[2][4] = fma2(ee2, kc[4], acc[2][4]);
            acc[3][4] = fma2(ee3, kc[4], acc[3][4]);

            #pragma unroll
            for (int h = 0; h < 5; h++) kc[h] = kn[h];
        }
        __syncthreads();   // all threads done with buffer b before refill
    }

    // intra-warp reduction over 32 key-part lanes
    #pragma unroll
    for (int off = 16; off >= 1; off >>= 1) {
        {
            u64 o01 = __shfl_down_sync(0xffffffffu, esum01, off);
            u64 o23 = __shfl_down_sync(0xffffffffu, esum23, off);
            esum01 = add2(esum01, o01);
            esum23 = add2(esum23, o23);
        }
        #pragma unroll
        for (int u = 0; u < QPT; u++)
            #pragma unroll
            for (int h = 0; h < 5; h++) {
                u64 other = __shfl_down_sync(0xffffffffu, acc[u][h], off);
                acc[u][h] = add2(acc[u][h], other);
            }
    }

    // cross-warp combine via SMEM overlay (all tile reads done)
    float* sred = &sk[0][0];    // [warp][u][12]: 10 acc + esum
    if (lane == 0) {
        float2 es01 = unpack2(esum01);
        float2 es23 = unpack2(esum23);
        float est[QPT] = {es01.x, es01.y, es23.x, es23.y};
        #pragma unroll
        for (int u = 0; u < QPT; u++) {
            float* dst = sred + (wid * QPT + u) * 12;
            #pragma unroll
            for (int h = 0; h < 5; h++) {
                float2 v = unpack2(acc[u][h]);
                dst[2 * h] = v.x; dst[2 * h + 1] = v.y;
            }
            dst[10] = est[u];
        }
    }
    __syncthreads();

    // 2 groups x 4 queries x 10 feats = 80 output elements
    if (tid < BQ * DIM) {
        int g = tid / (QPT * DIM);
        int u = (tid / DIM) % QPT;
        int f = tid % DIM;
        const float* w0p = sred + ((2 * g) * QPT + u) * 12;
        const float* w1p = sred + ((2 * g + 1) * QPT + u) * 12;
        float v  = w0p[f] + w1p[f];
        float es = w0p[10] + w1p[10];
        out[(blockIdx.x * BQ + g * QPT + u) * DIM + f] = v / es;
    }
}

// ---------------------------------------------------------------------------
extern "C" void kernel_launch(void* const* d_in, const int* in_sizes, int n_in,
                              void* d_out, int out_size) {
    const float* x = (const float*)d_in[0];   // [8192, 3, 10]
    const float* A = (const float*)d_in[1];   // [3, 3]
    const float* W = (const float*)d_in[2];   // [10, 10]
    float* out = (float*)d_out;               // [8192, 10]

    pooled_kernel<<<BATCH / PK_NT, PK_NT>>>(x, A, W);
    attn_kernel<<<BATCH / BQ, NT>>>(out);
}